// round 2
// baseline (speedup 1.0000x reference)
#include <cuda_runtime.h>
#include <cuda_bf16.h>

// GCN 2-layer:
//   deg[v] = #(dst==v) + 1 ; dinv = rsqrt(deg)
//   hs = (X @ W) * dinv[row]
//   agg[d] += hs[s]  (edges only)
//   out[v] = relu(dinv[v]*(agg[v] + hs[v]) + b)
// repeated twice (W1/b1 then W2/b2).
// NOTE: edge_index is int32 (JAX default x64-disabled downgrades int64).

#define MAXN 100000
#define HID 64
#define HID4 16   // HID/4 float4 per row

__device__ float4 g_hs [MAXN * HID4];   // scaled GEMM output (current layer)
__device__ float4 g_agg[MAXN * HID4];   // scatter accumulator
__device__ float4 g_h1 [MAXN * HID4];   // layer-1 output (layer-2 input)
__device__ float  g_dinv[MAXN];
__device__ int    g_deg [MAXN];

// ---------------------------------------------------------------------------
__global__ void deg_init_kernel(int n) {
    int i = blockIdx.x * blockDim.x + threadIdx.x;
    if (i < n) g_deg[i] = 1;  // self-loop
}

__global__ void deg_count_kernel(const int* __restrict__ dst, int E) {
    int i = blockIdx.x * blockDim.x + threadIdx.x;
    if (i < E) atomicAdd(&g_deg[dst[i]], 1);
}

__global__ void dinv_kernel(int n) {
    int i = blockIdx.x * blockDim.x + threadIdx.x;
    if (i < n) g_dinv[i] = rsqrtf((float)g_deg[i]);
}

__global__ void zero_agg_kernel(int n16) {
    int i = blockIdx.x * blockDim.x + threadIdx.x;
    if (i < n16) g_agg[i] = make_float4(0.f, 0.f, 0.f, 0.f);
}

// ---------------------------------------------------------------------------
// hs[row] = (X[row] @ W) * dinv[row]
// One row per warp. W (64x64 fp32, 16KB) in smem; x row staged in smem.
__global__ void gemm_scale_kernel(const float* __restrict__ X,
                                  const float* __restrict__ W,
                                  float4* __restrict__ out4, int n) {
    __shared__ float Ws[HID * HID];
    __shared__ float xs[8][HID];
    int tid = threadIdx.x;
    for (int i = tid; i < HID * HID; i += blockDim.x) Ws[i] = W[i];
    __syncthreads();

    int warp = tid >> 5, lane = tid & 31;
    float* out = (float*)out4;

    for (int row = blockIdx.x * 8 + warp; row < n; row += gridDim.x * 8) {
        float2 xv = ((const float2*)(X + (size_t)row * HID))[lane];
        xs[warp][2 * lane]     = xv.x;
        xs[warp][2 * lane + 1] = xv.y;
        __syncwarp();
        float a0 = 0.f, a1 = 0.f;
#pragma unroll
        for (int k = 0; k < HID; k++) {
            float xk = xs[warp][k];
            a0 = fmaf(xk, Ws[k * HID + lane],      a0);
            a1 = fmaf(xk, Ws[k * HID + lane + 32], a1);
        }
        float s = g_dinv[row];
        out[(size_t)row * HID + lane]      = a0 * s;
        out[(size_t)row * HID + lane + 32] = a1 * s;
        __syncwarp();
    }
}

// ---------------------------------------------------------------------------
// agg[dst] += hs[src]   — 16 threads per edge, one red.global.add.v4.f32 each
__global__ void scatter_kernel(const int* __restrict__ src,
                               const int* __restrict__ dst, int E) {
    long long gid = (long long)blockIdx.x * blockDim.x + threadIdx.x;
    if (gid >= (long long)E * HID4) return;
    int e = (int)(gid >> 4);
    int q = (int)(gid & 15);
    int s = __ldg(&src[e]);
    int d = __ldg(&dst[e]);
    float4 v = g_hs[(size_t)s * HID4 + q];
    float4* p = &g_agg[(size_t)d * HID4 + q];
    asm volatile("red.global.add.v4.f32 [%0], {%1,%2,%3,%4};"
                 :: "l"(p), "f"(v.x), "f"(v.y), "f"(v.z), "f"(v.w)
                 : "memory");
}

// ---------------------------------------------------------------------------
// out[v] = relu(dinv[v]*(agg[v]+hs[v]) + b)
__global__ void epilogue_kernel(const float* __restrict__ b,
                                float4* __restrict__ out, int n) {
    int idx = blockIdx.x * blockDim.x + threadIdx.x;
    if (idx >= n * HID4) return;
    int row = idx >> 4;
    int q   = idx & 15;
    float s = g_dinv[row];
    float4 a = g_agg[idx];
    float4 h = g_hs[idx];
    float4 bb = ((const float4*)b)[q];
    float4 r;
    r.x = fmaxf(fmaf(s, a.x + h.x, bb.x), 0.f);
    r.y = fmaxf(fmaf(s, a.y + h.y, bb.y), 0.f);
    r.z = fmaxf(fmaf(s, a.z + h.z, bb.z), 0.f);
    r.w = fmaxf(fmaf(s, a.w + h.w, bb.w), 0.f);
    out[idx] = r;
}

// ---------------------------------------------------------------------------
extern "C" void kernel_launch(void* const* d_in, const int* in_sizes, int n_in,
                              void* d_out, int out_size) {
    const float* x  = (const float*)d_in[0];
    const int*   ei = (const int*)d_in[1];
    const float* W1 = (const float*)d_in[2];
    const float* b1 = (const float*)d_in[3];
    const float* W2 = (const float*)d_in[4];
    const float* b2 = (const float*)d_in[5];
    float4* out = (float4*)d_out;

    int n = in_sizes[0] / HID;       // 100000
    int E = in_sizes[1] / 2;         // 1600000
    const int* src = ei;
    const int* dst = ei + E;

    float4* hs = nullptr; cudaGetSymbolAddress((void**)&hs, g_hs);
    float4* h1 = nullptr; cudaGetSymbolAddress((void**)&h1, g_h1);

    int n16 = n * HID4;
    long long scat_threads = (long long)E * HID4;
    int scat_blocks = (int)((scat_threads + 255) / 256);

    // degree + dinv (shared by both layers)
    deg_init_kernel<<<(n + 255) / 256, 256>>>(n);
    deg_count_kernel<<<(E + 255) / 256, 256>>>(dst, E);
    dinv_kernel<<<(n + 255) / 256, 256>>>(n);

    // ---- layer 1 ----
    gemm_scale_kernel<<<(n + 7) / 8, 256>>>(x, W1, hs, n);
    zero_agg_kernel<<<(n16 + 255) / 256, 256>>>(n16);
    scatter_kernel<<<scat_blocks, 256>>>(src, dst, E);
    epilogue_kernel<<<(n16 + 255) / 256, 256>>>(b1, (float4*)h1, n);

    // ---- layer 2 ----
    gemm_scale_kernel<<<(n + 7) / 8, 256>>>((const float*)h1, W2, hs, n);
    zero_agg_kernel<<<(n16 + 255) / 256, 256>>>(n16);
    scatter_kernel<<<scat_blocks, 256>>>(src, dst, E);
    epilogue_kernel<<<(n16 + 255) / 256, 256>>>(b2, out, n);
}

// round 3
// speedup vs baseline: 2.0672x; 2.0672x over previous
#include <cuda_runtime.h>
#include <cuda_bf16.h>

// GCN 2-layer, CSR-gather formulation:
//   deg[v] = in-edge count ; dinv = rsqrt(deg+1)
//   hs = (X @ W) * dinv[row]
//   out[v] = relu(dinv[v]*(sum_{s->v} hs[s] + hs[v]) + b)
// CSR (row_start, csr_src) built once per launch, reused by both layers.
// edge_index is int32.

#define MAXN 100000
#define HID 64
#define NEDGE_MAX 1600000
#define SCAN_B 512

__device__ float g_hs [MAXN * HID];     // scaled GEMM output (current layer)
__device__ float g_h1 [MAXN * HID];     // layer-1 output
__device__ float g_dinv[MAXN];
__device__ int   g_deg [MAXN];
__device__ int   g_rowstart[MAXN + 1];
__device__ int   g_cursor[MAXN];
__device__ int   g_csrc[NEDGE_MAX];
__device__ int   g_bsum[256];
__device__ int   g_boff[256];

// ---------------------------------------------------------------------------
__global__ void deg_init_kernel(int n) {
    int i = blockIdx.x * blockDim.x + threadIdx.x;
    if (i < n) g_deg[i] = 0;
}

__global__ void deg_count_kernel(const int* __restrict__ dst, int E) {
    int i = blockIdx.x * blockDim.x + threadIdx.x;
    if (i < E) atomicAdd(&g_deg[dst[i]], 1);
}

__global__ void dinv_kernel(int n) {
    int i = blockIdx.x * blockDim.x + threadIdx.x;
    if (i < n) g_dinv[i] = rsqrtf((float)(g_deg[i] + 1));
}

// ---- 3-kernel exclusive scan of g_deg -> g_rowstart --------------------------
__global__ void scan1_kernel(int n) {
    __shared__ int sm[SCAN_B];
    int tid = threadIdx.x;
    int i = blockIdx.x * SCAN_B + tid;
    int v = (i < n) ? g_deg[i] : 0;
    sm[tid] = v;
    __syncthreads();
#pragma unroll
    for (int off = 1; off < SCAN_B; off <<= 1) {
        int t = (tid >= off) ? sm[tid - off] : 0;
        __syncthreads();
        sm[tid] += t;
        __syncthreads();
    }
    if (i < n) g_rowstart[i] = sm[tid] - v;          // block-local exclusive
    if (tid == SCAN_B - 1) g_bsum[blockIdx.x] = sm[tid];
}

__global__ void scan2_kernel(int nb) {
    __shared__ int sm[256];
    int tid = threadIdx.x;
    int v = (tid < nb) ? g_bsum[tid] : 0;
    sm[tid] = v;
    __syncthreads();
#pragma unroll
    for (int off = 1; off < 256; off <<= 1) {
        int t = (tid >= off) ? sm[tid - off] : 0;
        __syncthreads();
        sm[tid] += t;
        __syncthreads();
    }
    if (tid < nb) g_boff[tid] = sm[tid] - v;
}

__global__ void scan3_kernel(int n, int E) {
    int i = blockIdx.x * blockDim.x + threadIdx.x;
    if (i < n) {
        int r = g_rowstart[i] + g_boff[i >> 9];
        g_rowstart[i] = r;
        g_cursor[i] = r;
    }
    if (i == 0) g_rowstart[n] = E;
}

__global__ void fill_kernel(const int* __restrict__ src,
                            const int* __restrict__ dst, int E) {
    int i = blockIdx.x * blockDim.x + threadIdx.x;
    if (i < E) {
        int pos = atomicAdd(&g_cursor[dst[i]], 1);
        g_csrc[pos] = src[i];
    }
}

// ---------------------------------------------------------------------------
// hs[row] = (X[row] @ W) * dinv[row]
// Block = 256 thr = 8 warps; each warp computes 4 rows x 64 cols.
// W (64x64) staged in smem; x tile (32 rows) staged in smem.
__global__ void gemm_scale_kernel(const float* __restrict__ X,
                                  const float* __restrict__ W,
                                  float* __restrict__ out, int n) {
    __shared__ float  Ws[HID * HID];     // 16 KB
    __shared__ float4 xs[32][16];        //  8 KB
    int tid = threadIdx.x;

    const float4* W4 = (const float4*)W;
    float4* Ws4 = (float4*)Ws;
#pragma unroll
    for (int i = tid; i < HID * HID / 4; i += 256) Ws4[i] = W4[i];

    int tile0 = blockIdx.x * 32;
    const float4* X4 = (const float4*)X;
#pragma unroll
    for (int i = tid; i < 32 * 16; i += 256) {
        int r = i >> 4, q = i & 15;
        int row = tile0 + r;
        xs[r][q] = (row < n) ? X4[(size_t)row * 16 + q]
                             : make_float4(0.f, 0.f, 0.f, 0.f);
    }
    __syncthreads();

    int warp = tid >> 5, lane = tid & 31;
    int r0 = warp * 4;

    float a00 = 0.f, a01 = 0.f, a10 = 0.f, a11 = 0.f;
    float a20 = 0.f, a21 = 0.f, a30 = 0.f, a31 = 0.f;

#pragma unroll
    for (int k4 = 0; k4 < 16; k4++) {
        float4 x0 = xs[r0 + 0][k4];
        float4 x1 = xs[r0 + 1][k4];
        float4 x2 = xs[r0 + 2][k4];
        float4 x3 = xs[r0 + 3][k4];
#pragma unroll
        for (int kk = 0; kk < 4; kk++) {
            int k = k4 * 4 + kk;
            float w0 = Ws[k * HID + lane];
            float w1 = Ws[k * HID + lane + 32];
            float e0 = (&x0.x)[kk], e1 = (&x1.x)[kk];
            float e2 = (&x2.x)[kk], e3 = (&x3.x)[kk];
            a00 = fmaf(e0, w0, a00);  a01 = fmaf(e0, w1, a01);
            a10 = fmaf(e1, w0, a10);  a11 = fmaf(e1, w1, a11);
            a20 = fmaf(e2, w0, a20);  a21 = fmaf(e2, w1, a21);
            a30 = fmaf(e3, w0, a30);  a31 = fmaf(e3, w1, a31);
        }
    }

    int row = tile0 + r0;
    if (row + 3 < n) {
        float s0 = g_dinv[row], s1 = g_dinv[row + 1];
        float s2 = g_dinv[row + 2], s3 = g_dinv[row + 3];
        out[(size_t)(row    ) * HID + lane]      = a00 * s0;
        out[(size_t)(row    ) * HID + lane + 32] = a01 * s0;
        out[(size_t)(row + 1) * HID + lane]      = a10 * s1;
        out[(size_t)(row + 1) * HID + lane + 32] = a11 * s1;
        out[(size_t)(row + 2) * HID + lane]      = a20 * s2;
        out[(size_t)(row + 2) * HID + lane + 32] = a21 * s2;
        out[(size_t)(row + 3) * HID + lane]      = a30 * s3;
        out[(size_t)(row + 3) * HID + lane + 32] = a31 * s3;
    } else {
        float acc0[4] = {a00, a10, a20, a30};
        float acc1[4] = {a01, a11, a21, a31};
        for (int i = 0; i < 4; i++) {
            int r = row + i;
            if (r < n) {
                float s = g_dinv[r];
                out[(size_t)r * HID + lane]      = acc0[i] * s;
                out[(size_t)r * HID + lane + 32] = acc1[i] * s;
            }
        }
    }
}

// ---------------------------------------------------------------------------
// One warp per node: acc = hs[v] + sum_{j in row} hs[csrc[j]];
// out[v] = relu(dinv[v]*acc + b)
__global__ void gather_kernel(const float* __restrict__ b,
                              float2* __restrict__ out, int n) {
    int w = (blockIdx.x * blockDim.x + threadIdx.x) >> 5;
    int lane = threadIdx.x & 31;
    if (w >= n) return;
    int v = w;
    int beg = g_rowstart[v];
    int end = g_rowstart[v + 1];
    const float2* hs2 = (const float2*)g_hs;

    float2 acc = hs2[(size_t)v * 32 + lane];   // self term
    int j = beg;
    for (; j + 4 <= end; j += 4) {
        int s0 = g_csrc[j], s1 = g_csrc[j + 1];
        int s2 = g_csrc[j + 2], s3 = g_csrc[j + 3];
        float2 a0 = hs2[(size_t)s0 * 32 + lane];
        float2 a1 = hs2[(size_t)s1 * 32 + lane];
        float2 a2 = hs2[(size_t)s2 * 32 + lane];
        float2 a3 = hs2[(size_t)s3 * 32 + lane];
        acc.x += (a0.x + a1.x) + (a2.x + a3.x);
        acc.y += (a0.y + a1.y) + (a2.y + a3.y);
    }
    for (; j < end; j++) {
        float2 a = hs2[(size_t)g_csrc[j] * 32 + lane];
        acc.x += a.x; acc.y += a.y;
    }
    float s = g_dinv[v];
    float2 bb = ((const float2*)b)[lane];
    float2 r;
    r.x = fmaxf(fmaf(s, acc.x, bb.x), 0.f);
    r.y = fmaxf(fmaf(s, acc.y, bb.y), 0.f);
    out[(size_t)v * 32 + lane] = r;
}

// ---------------------------------------------------------------------------
extern "C" void kernel_launch(void* const* d_in, const int* in_sizes, int n_in,
                              void* d_out, int out_size) {
    const float* x  = (const float*)d_in[0];
    const int*   ei = (const int*)d_in[1];
    const float* W1 = (const float*)d_in[2];
    const float* b1 = (const float*)d_in[3];
    const float* W2 = (const float*)d_in[4];
    const float* b2 = (const float*)d_in[5];

    int n = in_sizes[0] / HID;       // 100000
    int E = in_sizes[1] / 2;         // 1600000
    const int* src = ei;
    const int* dst = ei + E;

    float* hs = nullptr; cudaGetSymbolAddress((void**)&hs, g_hs);
    float* h1 = nullptr; cudaGetSymbolAddress((void**)&h1, g_h1);

    int nb_scan = (n + SCAN_B - 1) / SCAN_B;             // 196
    int gemm_blocks = (n + 31) / 32;                     // 3125
    int gather_blocks = (n * 32 + 255) / 256;            // 12500 (warp/node)

    // ---- degree + dinv + CSR (shared by both layers) ----
    deg_init_kernel<<<(n + 255) / 256, 256>>>(n);
    deg_count_kernel<<<(E + 255) / 256, 256>>>(dst, E);
    dinv_kernel<<<(n + 255) / 256, 256>>>(n);
    scan1_kernel<<<nb_scan, SCAN_B>>>(n);
    scan2_kernel<<<1, 256>>>(nb_scan);
    scan3_kernel<<<(n + 255) / 256, 256>>>(n, E);
    fill_kernel<<<(E + 255) / 256, 256>>>(src, dst, E);

    // ---- layer 1 ----
    gemm_scale_kernel<<<gemm_blocks, 256>>>(x, W1, hs, n);
    gather_kernel<<<gather_blocks, 256>>>(b1, (float2*)h1, n);

    // ---- layer 2 ----
    gemm_scale_kernel<<<gemm_blocks, 256>>>(h1, W2, hs, n);
    gather_kernel<<<gather_blocks, 256>>>(b2, (float2*)d_out, n);
}

// round 4
// speedup vs baseline: 2.1899x; 1.0593x over previous
#include <cuda_runtime.h>
#include <cuda_bf16.h>

// GCN 2-layer, CSR-gather formulation:
//   deg[v] = in-edge count ; dinv = rsqrt(deg+1)
//   hs = (X @ W) * dinv[row]          (f32x2-packed GEMM)
//   out[v] = relu(dinv[v]*(sum_{s->v} hs[s] + hs[v]) + b)
// CSR built once, reused by both layers. edge_index is int32.

#define MAXN 100000
#define HID 64
#define NEDGE_MAX 1600000
#define SCAN_B 512

__device__ float g_hs [MAXN * HID];
__device__ float g_h1 [MAXN * HID];
__device__ float g_dinv[MAXN];
__device__ int   g_deg [MAXN];
__device__ int   g_rowstart[MAXN + 1];
__device__ int   g_cursor[MAXN];
__device__ int   g_csrc[NEDGE_MAX];
__device__ int   g_bsum[256];
__device__ int   g_boff[256];

// packed fp32x2 fma: acc += a * b  (element-wise on both 32-bit halves)
__device__ __forceinline__ void fma2(float2& acc, const float2& a, const float2& b) {
    unsigned long long* pa = (unsigned long long*)&acc;
    asm("fma.rn.f32x2 %0, %1, %2, %0;"
        : "+l"(*pa)
        : "l"(*(const unsigned long long*)&a), "l"(*(const unsigned long long*)&b));
}

// ---------------------------------------------------------------------------
__global__ void deg_count_kernel(const int* __restrict__ dst, int E) {
    int i = blockIdx.x * blockDim.x + threadIdx.x;
    if (i < E) atomicAdd(&g_deg[dst[i]], 1);
}

// ---- 3-kernel exclusive scan of g_deg -> g_rowstart -------------------------
__global__ void scan1_kernel(int n) {
    __shared__ int sm[SCAN_B];
    int tid = threadIdx.x;
    int i = blockIdx.x * SCAN_B + tid;
    int v = (i < n) ? g_deg[i] : 0;
    sm[tid] = v;
    __syncthreads();
#pragma unroll
    for (int off = 1; off < SCAN_B; off <<= 1) {
        int t = (tid >= off) ? sm[tid - off] : 0;
        __syncthreads();
        sm[tid] += t;
        __syncthreads();
    }
    if (i < n) g_rowstart[i] = sm[tid] - v;
    if (tid == SCAN_B - 1) g_bsum[blockIdx.x] = sm[tid];
}

__global__ void scan2_kernel(int nb) {
    __shared__ int sm[256];
    int tid = threadIdx.x;
    int v = (tid < nb) ? g_bsum[tid] : 0;
    sm[tid] = v;
    __syncthreads();
#pragma unroll
    for (int off = 1; off < 256; off <<= 1) {
        int t = (tid >= off) ? sm[tid - off] : 0;
        __syncthreads();
        sm[tid] += t;
        __syncthreads();
    }
    if (tid < nb) g_boff[tid] = sm[tid] - v;
}

// also computes dinv and cursor init (fused)
__global__ void scan3_kernel(int n, int E) {
    int i = blockIdx.x * blockDim.x + threadIdx.x;
    if (i < n) {
        int r = g_rowstart[i] + g_boff[i >> 9];
        g_rowstart[i] = r;
        g_cursor[i] = r;
        g_dinv[i] = rsqrtf((float)(g_deg[i] + 1));
    }
    if (i == 0) g_rowstart[n] = E;
}

__global__ void fill_kernel(const int* __restrict__ src,
                            const int* __restrict__ dst, int E) {
    int i = blockIdx.x * blockDim.x + threadIdx.x;
    if (i < E) {
        int pos = atomicAdd(&g_cursor[dst[i]], 1);
        g_csrc[pos] = src[i];
    }
}

// ---------------------------------------------------------------------------
// hs[row] = (X[row] @ W) * dinv[row]
// Block = 256 thr = 8 warps; each warp computes 8 rows x 64 cols.
// f32x2 packing over k: acc halves hold even-k / odd-k partial sums.
// Wp[k2][col] = (W[2k2][col], W[2k2+1][col])  in smem.
__global__ void gemm_scale_kernel(const float* __restrict__ X,
                                  const float* __restrict__ W,
                                  float* __restrict__ out, int n) {
    __shared__ float2 Wp[32 * HID];      // 16 KB
    __shared__ float4 xs[64][16];        // 16 KB
    int tid = threadIdx.x;

    // stage W k-pair-interleaved
#pragma unroll
    for (int i = tid; i < 32 * HID; i += 256) {
        int k2 = i >> 6, col = i & 63;
        Wp[i] = make_float2(W[(2 * k2) * HID + col], W[(2 * k2 + 1) * HID + col]);
    }

    int tile0 = blockIdx.x * 64;
    const float4* X4 = (const float4*)X;
#pragma unroll
    for (int i = tid; i < 64 * 16; i += 256) {
        int r = i >> 4, q = i & 15;
        int row = tile0 + r;
        xs[r][q] = (row < n) ? X4[(size_t)row * 16 + q]
                             : make_float4(0.f, 0.f, 0.f, 0.f);
    }
    __syncthreads();

    int warp = tid >> 5, lane = tid & 31;
    int r0 = warp * 8;

    float2 accA[8], accB[8];   // col=lane, col=lane+32 ; halves = even/odd k
#pragma unroll
    for (int r = 0; r < 8; r++) {
        accA[r] = make_float2(0.f, 0.f);
        accB[r] = make_float2(0.f, 0.f);
    }

#pragma unroll
    for (int q = 0; q < 16; q++) {         // q covers k = 4q..4q+3  (k2 = 2q, 2q+1)
        float2 wA0 = Wp[(2 * q) * HID + lane];
        float2 wB0 = Wp[(2 * q) * HID + lane + 32];
        float2 wA1 = Wp[(2 * q + 1) * HID + lane];
        float2 wB1 = Wp[(2 * q + 1) * HID + lane + 32];
#pragma unroll
        for (int r = 0; r < 8; r++) {
            float4 xv = xs[r0 + r][q];
            float2 x0 = make_float2(xv.x, xv.y);
            float2 x1 = make_float2(xv.z, xv.w);
            fma2(accA[r], x0, wA0);
            fma2(accB[r], x0, wB0);
            fma2(accA[r], x1, wA1);
            fma2(accB[r], x1, wB1);
        }
    }

#pragma unroll
    for (int r = 0; r < 8; r++) {
        int row = tile0 + r0 + r;
        if (row < n) {
            float s = g_dinv[row];
            out[(size_t)row * HID + lane]      = (accA[r].x + accA[r].y) * s;
            out[(size_t)row * HID + lane + 32] = (accB[r].x + accB[r].y) * s;
        }
    }
}

// ---------------------------------------------------------------------------
// One warp per node: acc = hs[v] + sum_{j in row} hs[csrc[j]];
// out[v] = relu(dinv[v]*acc + b)
__global__ void gather_kernel(const float* __restrict__ b,
                              float2* __restrict__ out, int n) {
    int w = (blockIdx.x * blockDim.x + threadIdx.x) >> 5;
    int lane = threadIdx.x & 31;
    if (w >= n) return;
    int v = w;
    int beg = g_rowstart[v];
    int end = g_rowstart[v + 1];
    const float2* hs2 = (const float2*)g_hs;

    float2 acc = hs2[(size_t)v * 32 + lane];   // self term
    int j = beg;
    for (; j + 4 <= end; j += 4) {
        int s0 = g_csrc[j], s1 = g_csrc[j + 1];
        int s2 = g_csrc[j + 2], s3 = g_csrc[j + 3];
        float2 a0 = hs2[(size_t)s0 * 32 + lane];
        float2 a1 = hs2[(size_t)s1 * 32 + lane];
        float2 a2 = hs2[(size_t)s2 * 32 + lane];
        float2 a3 = hs2[(size_t)s3 * 32 + lane];
        acc.x += (a0.x + a1.x) + (a2.x + a3.x);
        acc.y += (a0.y + a1.y) + (a2.y + a3.y);
    }
    for (; j < end; j++) {
        float2 a = hs2[(size_t)g_csrc[j] * 32 + lane];
        acc.x += a.x; acc.y += a.y;
    }
    float s = g_dinv[v];
    float2 bb = ((const float2*)b)[lane];
    float2 r;
    r.x = fmaxf(fmaf(s, acc.x, bb.x), 0.f);
    r.y = fmaxf(fmaf(s, acc.y, bb.y), 0.f);
    out[(size_t)v * 32 + lane] = r;
}

// ---------------------------------------------------------------------------
extern "C" void kernel_launch(void* const* d_in, const int* in_sizes, int n_in,
                              void* d_out, int out_size) {
    const float* x  = (const float*)d_in[0];
    const int*   ei = (const int*)d_in[1];
    const float* W1 = (const float*)d_in[2];
    const float* b1 = (const float*)d_in[3];
    const float* W2 = (const float*)d_in[4];
    const float* b2 = (const float*)d_in[5];

    int n = in_sizes[0] / HID;       // 100000
    int E = in_sizes[1] / 2;         // 1600000
    const int* src = ei;
    const int* dst = ei + E;

    float* hs  = nullptr; cudaGetSymbolAddress((void**)&hs,  g_hs);
    float* h1  = nullptr; cudaGetSymbolAddress((void**)&h1,  g_h1);
    int*   deg = nullptr; cudaGetSymbolAddress((void**)&deg, g_deg);

    int nb_scan = (n + SCAN_B - 1) / SCAN_B;             // 196
    int gemm_blocks = (n + 63) / 64;                     // 1563
    int gather_blocks = (n * 32 + 255) / 256;            // 12500

    // ---- degree + CSR (shared by both layers) ----
    cudaMemsetAsync(deg, 0, n * sizeof(int));
    deg_count_kernel<<<(E + 255) / 256, 256>>>(dst, E);
    scan1_kernel<<<nb_scan, SCAN_B>>>(n);
    scan2_kernel<<<1, 256>>>(nb_scan);
    scan3_kernel<<<(n + 255) / 256, 256>>>(n, E);
    fill_kernel<<<(E + 255) / 256, 256>>>(src, dst, E);

    // ---- layer 1 ----
    gemm_scale_kernel<<<gemm_blocks, 256>>>(x, W1, hs, n);
    gather_kernel<<<gather_blocks, 256>>>(b1, (float2*)h1, n);

    // ---- layer 2 ----
    gemm_scale_kernel<<<gemm_blocks, 256>>>(h1, W2, hs, n);
    gather_kernel<<<gather_blocks, 256>>>(b2, (float2*)d_out, n);
}